// round 4
// baseline (speedup 1.0000x reference)
#include <cuda_runtime.h>
#include <cuda_bf16.h>
#include <cstdint>

// ---------------------------------------------------------------------------
// ViT encoder block. GEMMs: mma.sync bf16 2-term split (3 MMA terms),
// cp.async 4-stage pipelined, merged QKV. Attention + LayerNorm fp32 SIMT.
// ---------------------------------------------------------------------------

#define NTOK   16384
#define EMB    768
#define FFND   3072
#define HEADS  12
#define DK     64
#define SEQ    512
#define BATCH  32
#define QKVN   2304

// ----- fp32 scratch -----
__device__ __align__(128) float g_qkv[NTOK * QKVN];
__device__ __align__(128) float g_tmp[NTOK * EMB];
__device__ __align__(128) float g_x1 [NTOK * EMB];

// ----- bf16 split scratch -----
__device__ __align__(128) __nv_bfloat16 g_ah[NTOK * EMB];
__device__ __align__(128) __nv_bfloat16 g_al[NTOK * EMB];
__device__ __align__(128) __nv_bfloat16 g_ch[NTOK * EMB];
__device__ __align__(128) __nv_bfloat16 g_cl[NTOK * EMB];
__device__ __align__(128) __nv_bfloat16 g_fh[NTOK * FFND];
__device__ __align__(128) __nv_bfloat16 g_fl[NTOK * FFND];
#define WTOT 7077888
__device__ __align__(128) __nv_bfloat16 g_wh[WTOT];
__device__ __align__(128) __nv_bfloat16 g_wl[WTOT];

// ===========================================================================
// helpers
// ===========================================================================
__device__ __forceinline__ void ldsm4(uint32_t* r, const void* p) {
    uint32_t a = (uint32_t)__cvta_generic_to_shared(p);
    asm volatile("ldmatrix.sync.aligned.m8n8.x4.shared.b16 {%0,%1,%2,%3}, [%4];"
                 : "=r"(r[0]), "=r"(r[1]), "=r"(r[2]), "=r"(r[3]) : "r"(a));
}
__device__ __forceinline__ void ldsm4t(uint32_t* r, const void* p) {
    uint32_t a = (uint32_t)__cvta_generic_to_shared(p);
    asm volatile("ldmatrix.sync.aligned.m8n8.x4.trans.shared.b16 {%0,%1,%2,%3}, [%4];"
                 : "=r"(r[0]), "=r"(r[1]), "=r"(r[2]), "=r"(r[3]) : "r"(a));
}
__device__ __forceinline__ void mma16816(float* c, const uint32_t* a, const uint32_t* b) {
    asm volatile("mma.sync.aligned.m16n8k16.row.col.f32.bf16.bf16.f32 "
                 "{%0,%1,%2,%3}, {%4,%5,%6,%7}, {%8,%9}, {%0,%1,%2,%3};"
                 : "+f"(c[0]), "+f"(c[1]), "+f"(c[2]), "+f"(c[3])
                 : "r"(a[0]), "r"(a[1]), "r"(a[2]), "r"(a[3]), "r"(b[0]), "r"(b[1]));
}
__device__ __forceinline__ void cpa16(uint32_t dst, const void* src) {
    asm volatile("cp.async.cg.shared.global [%0], [%1], 16;" :: "r"(dst), "l"(src));
}
__device__ __forceinline__ void cpa_commit() {
    asm volatile("cp.async.commit_group;" ::: "memory");
}
__device__ __forceinline__ void cpa_wait2() {
    asm volatile("cp.async.wait_group 2;" ::: "memory");
}

// ===========================================================================
// split: fp32 -> bf16 hi + lo (contiguous, for activations)
// ===========================================================================
__global__ __launch_bounds__(256) void split_kernel(
    const float* __restrict__ in, __nv_bfloat16* __restrict__ h,
    __nv_bfloat16* __restrict__ l, int n)
{
    int i = (blockIdx.x * 256 + threadIdx.x) * 4;
    if (i >= n) return;
    float4 v = *(const float4*)(in + i);
    __nv_bfloat16 h0 = __float2bfloat16(v.x);
    __nv_bfloat16 h1 = __float2bfloat16(v.y);
    __nv_bfloat16 h2 = __float2bfloat16(v.z);
    __nv_bfloat16 h3 = __float2bfloat16(v.w);
    __nv_bfloat162 a; a.x = h0; a.y = h1;
    __nv_bfloat162 b; b.x = h2; b.y = h3;
    __nv_bfloat162 c; c.x = __float2bfloat16(v.x - __bfloat162float(h0));
    c.y = __float2bfloat16(v.y - __bfloat162float(h1));
    __nv_bfloat162 d; d.x = __float2bfloat16(v.z - __bfloat162float(h2));
    d.y = __float2bfloat16(v.w - __bfloat162float(h3));
    *reinterpret_cast<__nv_bfloat162*>(h + i)     = a;
    *reinterpret_cast<__nv_bfloat162*>(h + i + 2) = b;
    *reinterpret_cast<__nv_bfloat162*>(l + i)     = c;
    *reinterpret_cast<__nv_bfloat162*>(l + i + 2) = d;
}

// ===========================================================================
// splitw: W[K,N] fp32 -> merged hi/lo at column offset `off`, total width Ntot
// out[k*Ntot + off + n] = split(W[k*N + n])
// ===========================================================================
__global__ __launch_bounds__(256) void splitw_kernel(
    const float* __restrict__ W, __nv_bfloat16* __restrict__ h,
    __nv_bfloat16* __restrict__ l, int N, int Ntot, int off, int total)
{
    int i = (blockIdx.x * 256 + threadIdx.x) * 4;
    if (i >= total) return;
    int k = i / N, n = i - k * N;
    size_t o = (size_t)k * Ntot + off + n;
    float4 v = *(const float4*)(W + i);
    __nv_bfloat16 h0 = __float2bfloat16(v.x);
    __nv_bfloat16 h1 = __float2bfloat16(v.y);
    __nv_bfloat16 h2 = __float2bfloat16(v.z);
    __nv_bfloat16 h3 = __float2bfloat16(v.w);
    __nv_bfloat162 a; a.x = h0; a.y = h1;
    __nv_bfloat162 b; b.x = h2; b.y = h3;
    __nv_bfloat162 c; c.x = __float2bfloat16(v.x - __bfloat162float(h0));
    c.y = __float2bfloat16(v.y - __bfloat162float(h1));
    __nv_bfloat162 d; d.x = __float2bfloat16(v.z - __bfloat162float(h2));
    d.y = __float2bfloat16(v.w - __bfloat162float(h3));
    *reinterpret_cast<__nv_bfloat162*>(h + o)     = a;
    *reinterpret_cast<__nv_bfloat162*>(h + o + 2) = b;
    *reinterpret_cast<__nv_bfloat162*>(l + o)     = c;
    *reinterpret_cast<__nv_bfloat162*>(l + o + 2) = d;
}

// ===========================================================================
// GEMM: C[M,N] = A[M,K] @ B[K,N]; A/B bf16 hi/lo. 128x128 tile, BK=16,
// 256 threads, 4-stage cp.async pipeline.
// EPI: 0 = fp32 C; 1 = +bias fp32 C; 3 = +bias+relu -> bf16 split Ch/Cl
// ===========================================================================
#define ASTR 24
#define BSTR 136
// per-stage bytes: Ah 6144 | Al 6144 | Bh 4352 | Bl 4352
#define ST_AL 6144
#define ST_BH 12288
#define ST_BL 16640
#define ST_SZ 20992
#define NSTG  4
#define GSMEM (NSTG * ST_SZ)   // 83968

template <int EPI>
__global__ __launch_bounds__(256, 1) void tgemm(
    const __nv_bfloat16* __restrict__ Ah, const __nv_bfloat16* __restrict__ Al,
    const __nv_bfloat16* __restrict__ Bh, const __nv_bfloat16* __restrict__ Bl,
    const float* __restrict__ bias, float* __restrict__ C,
    __nv_bfloat16* __restrict__ Ch, __nv_bfloat16* __restrict__ Cl,
    int M, int N, int K)
{
    extern __shared__ char smem[];
    const uint32_t sb = (uint32_t)__cvta_generic_to_shared(smem);

    const int tid  = threadIdx.x;
    const int lane = tid & 31;
    const int w    = tid >> 5;
    const int wm   = w & 3;
    const int wn   = w >> 2;
    const int bm   = blockIdx.y * 128;
    const int bn   = blockIdx.x * 128;

    // loaders
    const int ar  = tid >> 1;          // 0..127
    const int ac  = (tid & 1) * 8;     // 0 / 8 (elems)
    const int br  = tid >> 4;          // 0..15
    const int bc  = (tid & 15) * 8;    // 0..120

    const __nv_bfloat16* gAh = Ah + (size_t)(bm + ar) * K + ac;
    const __nv_bfloat16* gAl = Al + (size_t)(bm + ar) * K + ac;
    const __nv_bfloat16* gBh = Bh + (size_t)br * N + bn + bc;
    const __nv_bfloat16* gBl = Bl + (size_t)br * N + bn + bc;

    const uint32_t dA = sb + (uint32_t)(ar * ASTR + ac) * 2;
    const uint32_t dB = sb + (uint32_t)(br * BSTR + bc) * 2;

    auto load_stage = [&](int s, int kt) {
        const uint32_t o = (uint32_t)s * ST_SZ;
        const int k0 = kt * 16;
        cpa16(dA + o,         gAh + k0);
        cpa16(dA + o + ST_AL, gAl + k0);
        cpa16(dB + o + ST_BH, gBh + (size_t)k0 * N);
        cpa16(dB + o + ST_BL, gBl + (size_t)k0 * N);
    };

    // ldmatrix offsets (element units within a stage)
    int a_off[2];
#pragma unroll
    for (int mi = 0; mi < 2; mi++) {
        int row = wm * 32 + mi * 16 + (lane & 15);
        int col = (lane >> 4) * 8;
        a_off[mi] = row * ASTR + col;
    }
    int b_off[4];
    {
        int krow = lane & 15;
#pragma unroll
        for (int p = 0; p < 4; p++) {
            int col = wn * 64 + (p * 2 + (lane >> 4)) * 8;
            b_off[p] = krow * BSTR + col;
        }
    }

    float c[2][8][4];
#pragma unroll
    for (int mi = 0; mi < 2; mi++)
#pragma unroll
        for (int ni = 0; ni < 8; ni++)
#pragma unroll
            for (int e = 0; e < 4; e++) c[mi][ni][e] = 0.f;

    const int NK = K >> 4;

    // prologue: stages 0..2
#pragma unroll
    for (int s = 0; s < 3; s++) {
        load_stage(s, s);
        cpa_commit();
    }

    for (int kt = 0; kt < NK; kt++) {
        cpa_wait2();
        __syncthreads();
        if (kt + 3 < NK) load_stage((kt + 3) & (NSTG - 1), kt + 3);
        cpa_commit();

        const uint32_t so = (uint32_t)(kt & (NSTG - 1)) * ST_SZ;
        const char* stg = smem + so;

        uint32_t fah[2][4], fal[2][4], fbh[8][2], fbl[8][2];
#pragma unroll
        for (int mi = 0; mi < 2; mi++) {
            ldsm4(fah[mi], stg + a_off[mi] * 2);
            ldsm4(fal[mi], stg + ST_AL + a_off[mi] * 2);
        }
#pragma unroll
        for (int p = 0; p < 4; p++) {
            uint32_t r[4];
            ldsm4t(r, stg + ST_BH + b_off[p] * 2);
            fbh[p * 2][0] = r[0]; fbh[p * 2][1] = r[1];
            fbh[p * 2 + 1][0] = r[2]; fbh[p * 2 + 1][1] = r[3];
            ldsm4t(r, stg + ST_BL + b_off[p] * 2);
            fbl[p * 2][0] = r[0]; fbl[p * 2][1] = r[1];
            fbl[p * 2 + 1][0] = r[2]; fbl[p * 2 + 1][1] = r[3];
        }

#pragma unroll
        for (int mi = 0; mi < 2; mi++)
#pragma unroll
            for (int ni = 0; ni < 8; ni++) mma16816(c[mi][ni], fah[mi], fbh[ni]);
#pragma unroll
        for (int mi = 0; mi < 2; mi++)
#pragma unroll
            for (int ni = 0; ni < 8; ni++) mma16816(c[mi][ni], fah[mi], fbl[ni]);
#pragma unroll
        for (int mi = 0; mi < 2; mi++)
#pragma unroll
            for (int ni = 0; ni < 8; ni++) mma16816(c[mi][ni], fal[mi], fbh[ni]);
    }

    // epilogue
    const int er = lane >> 2;
    const int ec = (lane & 3) * 2;
#pragma unroll
    for (int mi = 0; mi < 2; mi++) {
#pragma unroll
        for (int ni = 0; ni < 8; ni++) {
            int r0 = bm + wm * 32 + mi * 16 + er;
            int cc = bn + wn * 64 + ni * 8 + ec;
            float v0 = c[mi][ni][0], v1 = c[mi][ni][1];
            float v2 = c[mi][ni][2], v3 = c[mi][ni][3];
            if (EPI >= 1) {
                float bi0 = bias[cc], bi1 = bias[cc + 1];
                v0 += bi0; v1 += bi1; v2 += bi0; v3 += bi1;
            }
            if (EPI == 3) {
                v0 = fmaxf(v0, 0.f); v1 = fmaxf(v1, 0.f);
                v2 = fmaxf(v2, 0.f); v3 = fmaxf(v3, 0.f);
                __nv_bfloat16 h0 = __float2bfloat16(v0);
                __nv_bfloat16 h1 = __float2bfloat16(v1);
                __nv_bfloat16 h2 = __float2bfloat16(v2);
                __nv_bfloat16 h3 = __float2bfloat16(v3);
                __nv_bfloat162 hp0; hp0.x = h0; hp0.y = h1;
                __nv_bfloat162 hp1; hp1.x = h2; hp1.y = h3;
                __nv_bfloat162 lp0;
                lp0.x = __float2bfloat16(v0 - __bfloat162float(h0));
                lp0.y = __float2bfloat16(v1 - __bfloat162float(h1));
                __nv_bfloat162 lp1;
                lp1.x = __float2bfloat16(v2 - __bfloat162float(h2));
                lp1.y = __float2bfloat16(v3 - __bfloat162float(h3));
                *reinterpret_cast<__nv_bfloat162*>(&Ch[(size_t)r0 * N + cc])       = hp0;
                *reinterpret_cast<__nv_bfloat162*>(&Cl[(size_t)r0 * N + cc])       = lp0;
                *reinterpret_cast<__nv_bfloat162*>(&Ch[(size_t)(r0 + 8) * N + cc]) = hp1;
                *reinterpret_cast<__nv_bfloat162*>(&Cl[(size_t)(r0 + 8) * N + cc]) = lp1;
            } else {
                *(float2*)&C[(size_t)r0 * N + cc]       = make_float2(v0, v1);
                *(float2*)&C[(size_t)(r0 + 8) * N + cc] = make_float2(v2, v3);
            }
        }
    }
}

// ===========================================================================
// Attention (fp32 SIMT) reading fused QKV [NTOK, 2304]; ctx -> bf16 split.
// ===========================================================================
__global__ __launch_bounds__(256) void attn_kernel(
    const float* __restrict__ QKV,
    __nv_bfloat16* __restrict__ Oh, __nv_bfloat16* __restrict__ Ol)
{
    extern __shared__ float sm[];
    float* sQ  = sm;
    float* sK  = sQ + 2048;
    float* sKt = sK + 4096;
    float* sS  = sKt + 4352;

    const int qt  = blockIdx.x;
    const int h   = blockIdx.y;
    const int b   = blockIdx.z;
    const int tid = threadIdx.x;
    const size_t base = (size_t)b * SEQ * QKVN + h * DK;

    for (int i = tid; i < 512; i += 256) {
        int r = i >> 4, cx = (i & 15) * 4;
        *(float4*)&sQ[r * 64 + cx] =
            *(const float4*)&QKV[base + (size_t)(qt * 32 + r) * QKVN + cx];
    }

    const int gq  = tid >> 4;
    const int gk  = tid & 15;
    const int qi0 = gq * 2;
    const int kj0 = gk * 4;

    for (int kt = 0; kt < 8; kt++) {
        __syncthreads();
        for (int i = tid; i < 1024; i += 256) {
            int r = i >> 4, cx = (i & 15) * 4;
            *(float4*)&sK[r * 64 + cx] =
                *(const float4*)&QKV[base + 768 + (size_t)(kt * 64 + r) * QKVN + cx];
        }
        __syncthreads();
        for (int i = tid; i < 4096; i += 256) {
            int d = i & 63, r = i >> 6;
            sKt[d * 68 + r] = sK[r * 64 + d];
        }
        __syncthreads();

        float acc[2][4] = {{0.f,0.f,0.f,0.f},{0.f,0.f,0.f,0.f}};
#pragma unroll 8
        for (int d = 0; d < 64; d++) {
            float q0 = sQ[qi0 * 64 + d];
            float q1 = sQ[qi0 * 64 + 64 + d];
            float4 kv = *(float4*)&sKt[d * 68 + kj0];
            acc[0][0] += q0 * kv.x; acc[0][1] += q0 * kv.y;
            acc[0][2] += q0 * kv.z; acc[0][3] += q0 * kv.w;
            acc[1][0] += q1 * kv.x; acc[1][1] += q1 * kv.y;
            acc[1][2] += q1 * kv.z; acc[1][3] += q1 * kv.w;
        }
#pragma unroll
        for (int i = 0; i < 2; i++)
#pragma unroll
            for (int j = 0; j < 4; j++)
                sS[(qi0 + i) * 512 + kt * 64 + kj0 + j] = acc[i][j] * 0.125f;
    }
    __syncthreads();

    {
        const int wid = tid >> 5, lanei = tid & 31;
        for (int r = wid * 4; r < wid * 4 + 4; r++) {
            float* srow = sS + r * 512;
            float m = -1e30f;
            for (int cx = lanei; cx < 512; cx += 32) m = fmaxf(m, srow[cx]);
#pragma unroll
            for (int o = 16; o > 0; o >>= 1)
                m = fmaxf(m, __shfl_xor_sync(0xffffffffu, m, o));
            float s = 0.f;
            for (int cx = lanei; cx < 512; cx += 32) {
                float e = __expf(srow[cx] - m);
                srow[cx] = e;
                s += e;
            }
#pragma unroll
            for (int o = 16; o > 0; o >>= 1)
                s += __shfl_xor_sync(0xffffffffu, s, o);
            float inv = 1.0f / s;
            for (int cx = lanei; cx < 512; cx += 32) srow[cx] *= inv;
        }
    }

    const int d0 = gk * 4;
    float o_[2][4] = {{0.f,0.f,0.f,0.f},{0.f,0.f,0.f,0.f}};
    for (int kt = 0; kt < 8; kt++) {
        __syncthreads();
        for (int i = tid; i < 1024; i += 256) {
            int r = i >> 4, cx = (i & 15) * 4;
            *(float4*)&sK[r * 64 + cx] =
                *(const float4*)&QKV[base + 1536 + (size_t)(kt * 64 + r) * QKVN + cx];
        }
        __syncthreads();
#pragma unroll 4
        for (int k = 0; k < 64; k++) {
            float s0 = sS[qi0 * 512 + kt * 64 + k];
            float s1 = sS[qi0 * 512 + 512 + kt * 64 + k];
            float4 vv = *(float4*)&sK[k * 64 + d0];
            o_[0][0] += s0 * vv.x; o_[0][1] += s0 * vv.y;
            o_[0][2] += s0 * vv.z; o_[0][3] += s0 * vv.w;
            o_[1][0] += s1 * vv.x; o_[1][1] += s1 * vv.y;
            o_[1][2] += s1 * vv.z; o_[1][3] += s1 * vv.w;
        }
    }

#pragma unroll
    for (int i = 0; i < 2; i++) {
        size_t idx = ((size_t)b * SEQ + qt * 32 + qi0 + i) * EMB + h * DK + d0;
        __nv_bfloat16 h0 = __float2bfloat16(o_[i][0]);
        __nv_bfloat16 h1 = __float2bfloat16(o_[i][1]);
        __nv_bfloat16 h2 = __float2bfloat16(o_[i][2]);
        __nv_bfloat16 h3 = __float2bfloat16(o_[i][3]);
        __nv_bfloat162 hp0; hp0.x = h0; hp0.y = h1;
        __nv_bfloat162 hp1; hp1.x = h2; hp1.y = h3;
        __nv_bfloat162 lp0;
        lp0.x = __float2bfloat16(o_[i][0] - __bfloat162float(h0));
        lp0.y = __float2bfloat16(o_[i][1] - __bfloat162float(h1));
        __nv_bfloat162 lp1;
        lp1.x = __float2bfloat16(o_[i][2] - __bfloat162float(h2));
        lp1.y = __float2bfloat16(o_[i][3] - __bfloat162float(h3));
        *reinterpret_cast<__nv_bfloat162*>(&Oh[idx])     = hp0;
        *reinterpret_cast<__nv_bfloat162*>(&Oh[idx + 2]) = hp1;
        *reinterpret_cast<__nv_bfloat162*>(&Ol[idx])     = lp0;
        *reinterpret_cast<__nv_bfloat162*>(&Ol[idx + 2]) = lp1;
    }
}

// ===========================================================================
// Fused residual + LayerNorm (+ optional bf16 split out)
// ===========================================================================
__global__ __launch_bounds__(256) void add_ln_kernel(
    const float* __restrict__ x, const float* __restrict__ r,
    const float* __restrict__ gamma, const float* __restrict__ beta,
    float* __restrict__ out,
    __nv_bfloat16* __restrict__ oh, __nv_bfloat16* __restrict__ ol)
{
    const int row = blockIdx.x;
    const int tid = threadIdx.x;
    const float* xr = x + (size_t)row * EMB;
    const float* rr = r + (size_t)row * EMB;

    float v[3];
    float s = 0.f;
#pragma unroll
    for (int i = 0; i < 3; i++) {
        int cx = tid + i * 256;
        float t = xr[cx] + rr[cx];
        v[i] = t;
        s += t;
    }

    __shared__ float red[8];
    const int wid = tid >> 5, lane = tid & 31;
#pragma unroll
    for (int o = 16; o > 0; o >>= 1) s += __shfl_xor_sync(0xffffffffu, s, o);
    if (lane == 0) red[wid] = s;
    __syncthreads();
    if (tid == 0) {
        float t = 0.f;
#pragma unroll
        for (int i = 0; i < 8; i++) t += red[i];
        red[0] = t;
    }
    __syncthreads();
    const float mean = red[0] * (1.0f / 768.0f);

    float s2 = 0.f;
#pragma unroll
    for (int i = 0; i < 3; i++) {
        float d = v[i] - mean;
        s2 += d * d;
    }
#pragma unroll
    for (int o = 16; o > 0; o >>= 1) s2 += __shfl_xor_sync(0xffffffffu, s2, o);
    __syncthreads();
    if (lane == 0) red[wid] = s2;
    __syncthreads();
    if (tid == 0) {
        float t = 0.f;
#pragma unroll
        for (int i = 0; i < 8; i++) t += red[i];
        red[0] = t;
    }
    __syncthreads();
    const float var  = red[0] * (1.0f / 768.0f);
    const float rstd = rsqrtf(var + 1e-5f);

#pragma unroll
    for (int i = 0; i < 3; i++) {
        int cx = tid + i * 256;
        float o = (v[i] - mean) * rstd * gamma[cx] + beta[cx];
        size_t idx = (size_t)row * EMB + cx;
        out[idx] = o;
        if (oh) {
            __nv_bfloat16 hh = __float2bfloat16(o);
            oh[idx] = hh;
            ol[idx] = __float2bfloat16(o - __bfloat162float(hh));
        }
    }
}

// ===========================================================================
// Launch
// ===========================================================================
extern "C" void kernel_launch(void* const* d_in, const int* in_sizes, int n_in,
                              void* d_out, int out_size)
{
    (void)in_sizes; (void)n_in; (void)out_size;

    const float* x   = (const float*)d_in[0];
    const float* Wq  = (const float*)d_in[1];
    const float* Wk  = (const float*)d_in[2];
    const float* Wv  = (const float*)d_in[3];
    const float* Wo  = (const float*)d_in[4];
    const float* W1  = (const float*)d_in[5];
    const float* b1  = (const float*)d_in[6];
    const float* W2  = (const float*)d_in[7];
    const float* b2  = (const float*)d_in[8];
    const float* g1  = (const float*)d_in[9];
    const float* be1 = (const float*)d_in[10];
    const float* g2  = (const float*)d_in[11];
    const float* be2 = (const float*)d_in[12];
    float* out = (float*)d_out;

    float *qkv, *tmp, *x1;
    __nv_bfloat16 *ah, *al, *ch, *cl, *fh, *fl, *wh, *wl;
    cudaGetSymbolAddress((void**)&qkv, g_qkv);
    cudaGetSymbolAddress((void**)&tmp, g_tmp);
    cudaGetSymbolAddress((void**)&x1,  g_x1);
    cudaGetSymbolAddress((void**)&ah,  g_ah);
    cudaGetSymbolAddress((void**)&al,  g_al);
    cudaGetSymbolAddress((void**)&ch,  g_ch);
    cudaGetSymbolAddress((void**)&cl,  g_cl);
    cudaGetSymbolAddress((void**)&fh,  g_fh);
    cudaGetSymbolAddress((void**)&fl,  g_fl);
    cudaGetSymbolAddress((void**)&wh,  g_wh);
    cudaGetSymbolAddress((void**)&wl,  g_wl);

    const int ATTN_SMEM = (2048 + 4096 + 64 * 68 + 16384) * 4;
    cudaFuncSetAttribute(attn_kernel,
                         cudaFuncAttributeMaxDynamicSharedMemorySize, ATTN_SMEM);
    cudaFuncSetAttribute(tgemm<0>,
                         cudaFuncAttributeMaxDynamicSharedMemorySize, GSMEM);
    cudaFuncSetAttribute(tgemm<1>,
                         cudaFuncAttributeMaxDynamicSharedMemorySize, GSMEM);
    cudaFuncSetAttribute(tgemm<3>,
                         cudaFuncAttributeMaxDynamicSharedMemorySize, GSMEM);

    const size_t EE = (size_t)EMB * EMB;         // 589824
    const size_t EF = (size_t)EMB * FFND;        // 2359296
    // weight buffer layout: [ QKV merged (768x2304) | Wo | W1 | W2 ]
    const size_t OQKV = 0, OO_ = 3 * EE, O1_ = 4 * EE, O2_ = 4 * EE + EF;

    dim3 blk(256);

    // activation split (x)
    split_kernel<<<NTOK * EMB / 1024, blk>>>(x, ah, al, NTOK * EMB);
    // weight splits; Wq/Wk/Wv scatter into merged [768,2304] buffer
    splitw_kernel<<<(int)(EE / 1024), blk>>>(Wq, wh + OQKV, wl + OQKV, EMB, QKVN, 0,    (int)EE);
    splitw_kernel<<<(int)(EE / 1024), blk>>>(Wk, wh + OQKV, wl + OQKV, EMB, QKVN, 768,  (int)EE);
    splitw_kernel<<<(int)(EE / 1024), blk>>>(Wv, wh + OQKV, wl + OQKV, EMB, QKVN, 1536, (int)EE);
    splitw_kernel<<<(int)(EE / 1024), blk>>>(Wo, wh + OO_,  wl + OO_,  EMB, EMB,  0,    (int)EE);
    splitw_kernel<<<(int)(EF / 1024), blk>>>(W1, wh + O1_,  wl + O1_,  FFND, FFND, 0,   (int)EF);
    splitw_kernel<<<(int)(EF / 1024), blk>>>(W2, wh + O2_,  wl + O2_,  EMB,  EMB,  0,   (int)EF);

    // fused QKV projection: [NTOK,768] @ [768,2304]
    tgemm<0><<<dim3(QKVN / 128, NTOK / 128), blk, GSMEM>>>(
        ah, al, wh + OQKV, wl + OQKV, nullptr, qkv, nullptr, nullptr, NTOK, QKVN, EMB);

    // attention -> ctx (bf16 split)
    attn_kernel<<<dim3(SEQ / 32, HEADS, BATCH), blk, ATTN_SMEM>>>(qkv, ch, cl);

    // output projection
    tgemm<0><<<dim3(EMB / 128, NTOK / 128), blk, GSMEM>>>(
        ch, cl, wh + OO_, wl + OO_, nullptr, tmp, nullptr, nullptr, NTOK, EMB, EMB);

    // residual + LN1 (emits x1 split into ah/al)
    add_ln_kernel<<<NTOK, blk>>>(x, tmp, g1, be1, x1, ah, al);

    // FFN
    tgemm<3><<<dim3(FFND / 128, NTOK / 128), blk, GSMEM>>>(
        ah, al, wh + O1_, wl + O1_, b1, nullptr, fh, fl, NTOK, FFND, EMB);
    tgemm<1><<<dim3(EMB / 128, NTOK / 128), blk, GSMEM>>>(
        fh, fl, wh + O2_, wl + O2_, b2, tmp, nullptr, nullptr, NTOK, EMB, FFND);

    // residual + LN2
    add_ln_kernel<<<NTOK, blk>>>(x1, tmp, g2, be2, out, nullptr, nullptr);
}

// round 5
// speedup vs baseline: 1.2297x; 1.2297x over previous
#include <cuda_runtime.h>
#include <cuda_bf16.h>
#include <cstdint>

// ---------------------------------------------------------------------------
// ViT encoder block. GEMMs: mma.sync bf16 2-term split (3 MMA terms),
// register-prefetch double-buffered smem, single barrier per k-iter,
// merged QKV. Attention + LayerNorm fp32 SIMT.
// ---------------------------------------------------------------------------

#define NTOK   16384
#define EMB    768
#define FFND   3072
#define HEADS  12
#define DK     64
#define SEQ    512
#define BATCH  32
#define QKVN   2304

// ----- fp32 scratch -----
__device__ __align__(128) float g_qkv[NTOK * QKVN];
__device__ __align__(128) float g_tmp[NTOK * EMB];
__device__ __align__(128) float g_x1 [NTOK * EMB];

// ----- bf16 split scratch -----
__device__ __align__(128) __nv_bfloat16 g_ah[NTOK * EMB];
__device__ __align__(128) __nv_bfloat16 g_al[NTOK * EMB];
__device__ __align__(128) __nv_bfloat16 g_ch[NTOK * EMB];
__device__ __align__(128) __nv_bfloat16 g_cl[NTOK * EMB];
__device__ __align__(128) __nv_bfloat16 g_fh[NTOK * FFND];
__device__ __align__(128) __nv_bfloat16 g_fl[NTOK * FFND];
#define WTOT 7077888
__device__ __align__(128) __nv_bfloat16 g_wh[WTOT];
__device__ __align__(128) __nv_bfloat16 g_wl[WTOT];

// ===========================================================================
// helpers
// ===========================================================================
__device__ __forceinline__ void ldsm4(uint32_t* r, const void* p) {
    uint32_t a = (uint32_t)__cvta_generic_to_shared(p);
    asm volatile("ldmatrix.sync.aligned.m8n8.x4.shared.b16 {%0,%1,%2,%3}, [%4];"
                 : "=r"(r[0]), "=r"(r[1]), "=r"(r[2]), "=r"(r[3]) : "r"(a));
}
__device__ __forceinline__ void ldsm4t(uint32_t* r, const void* p) {
    uint32_t a = (uint32_t)__cvta_generic_to_shared(p);
    asm volatile("ldmatrix.sync.aligned.m8n8.x4.trans.shared.b16 {%0,%1,%2,%3}, [%4];"
                 : "=r"(r[0]), "=r"(r[1]), "=r"(r[2]), "=r"(r[3]) : "r"(a));
}
__device__ __forceinline__ void mma16816(float* c, const uint32_t* a, const uint32_t* b) {
    asm volatile("mma.sync.aligned.m16n8k16.row.col.f32.bf16.bf16.f32 "
                 "{%0,%1,%2,%3}, {%4,%5,%6,%7}, {%8,%9}, {%0,%1,%2,%3};"
                 : "+f"(c[0]), "+f"(c[1]), "+f"(c[2]), "+f"(c[3])
                 : "r"(a[0]), "r"(a[1]), "r"(a[2]), "r"(a[3]), "r"(b[0]), "r"(b[1]));
}

// ===========================================================================
// split: fp32 -> bf16 hi + lo (contiguous, for activations)
// ===========================================================================
__global__ __launch_bounds__(256) void split_kernel(
    const float* __restrict__ in, __nv_bfloat16* __restrict__ h,
    __nv_bfloat16* __restrict__ l, int n)
{
    int i = (blockIdx.x * 256 + threadIdx.x) * 4;
    if (i >= n) return;
    float4 v = *(const float4*)(in + i);
    __nv_bfloat16 h0 = __float2bfloat16(v.x);
    __nv_bfloat16 h1 = __float2bfloat16(v.y);
    __nv_bfloat16 h2 = __float2bfloat16(v.z);
    __nv_bfloat16 h3 = __float2bfloat16(v.w);
    __nv_bfloat162 a; a.x = h0; a.y = h1;
    __nv_bfloat162 b; b.x = h2; b.y = h3;
    __nv_bfloat162 c; c.x = __float2bfloat16(v.x - __bfloat162float(h0));
    c.y = __float2bfloat16(v.y - __bfloat162float(h1));
    __nv_bfloat162 d; d.x = __float2bfloat16(v.z - __bfloat162float(h2));
    d.y = __float2bfloat16(v.w - __bfloat162float(h3));
    *reinterpret_cast<__nv_bfloat162*>(h + i)     = a;
    *reinterpret_cast<__nv_bfloat162*>(h + i + 2) = b;
    *reinterpret_cast<__nv_bfloat162*>(l + i)     = c;
    *reinterpret_cast<__nv_bfloat162*>(l + i + 2) = d;
}

// ===========================================================================
// splitw: W[K,N] fp32 -> merged hi/lo at column offset `off`, width Ntot
// ===========================================================================
__global__ __launch_bounds__(256) void splitw_kernel(
    const float* __restrict__ W, __nv_bfloat16* __restrict__ h,
    __nv_bfloat16* __restrict__ l, int N, int Ntot, int off, int total)
{
    int i = (blockIdx.x * 256 + threadIdx.x) * 4;
    if (i >= total) return;
    int k = i / N, n = i - k * N;
    size_t o = (size_t)k * Ntot + off + n;
    float4 v = *(const float4*)(W + i);
    __nv_bfloat16 h0 = __float2bfloat16(v.x);
    __nv_bfloat16 h1 = __float2bfloat16(v.y);
    __nv_bfloat16 h2 = __float2bfloat16(v.z);
    __nv_bfloat16 h3 = __float2bfloat16(v.w);
    __nv_bfloat162 a; a.x = h0; a.y = h1;
    __nv_bfloat162 b; b.x = h2; b.y = h3;
    __nv_bfloat162 c; c.x = __float2bfloat16(v.x - __bfloat162float(h0));
    c.y = __float2bfloat16(v.y - __bfloat162float(h1));
    __nv_bfloat162 d; d.x = __float2bfloat16(v.z - __bfloat162float(h2));
    d.y = __float2bfloat16(v.w - __bfloat162float(h3));
    *reinterpret_cast<__nv_bfloat162*>(h + o)     = a;
    *reinterpret_cast<__nv_bfloat162*>(h + o + 2) = b;
    *reinterpret_cast<__nv_bfloat162*>(l + o)     = c;
    *reinterpret_cast<__nv_bfloat162*>(l + o + 2) = d;
}

// ===========================================================================
// GEMM: C[M,N] = A[M,K] @ B[K,N]; A/B bf16 hi/lo. 128x128 tile, BK=16,
// 256 threads, register prefetch + double-buffered smem, ONE sync per iter.
// EPI: 0 = fp32 C; 1 = +bias fp32 C; 3 = +bias+relu -> bf16 split Ch/Cl
// ===========================================================================
#define ASTR 24    // A smem row stride (elems)
#define BSTR 136   // B smem row stride

template <int EPI>
__global__ __launch_bounds__(256) void tgemm(
    const __nv_bfloat16* __restrict__ Ah, const __nv_bfloat16* __restrict__ Al,
    const __nv_bfloat16* __restrict__ Bh, const __nv_bfloat16* __restrict__ Bl,
    const float* __restrict__ bias, float* __restrict__ C,
    __nv_bfloat16* __restrict__ Ch, __nv_bfloat16* __restrict__ Cl,
    int M, int N, int K)
{
    __shared__ __align__(16) __nv_bfloat16 sAh[2][128 * ASTR];
    __shared__ __align__(16) __nv_bfloat16 sAl[2][128 * ASTR];
    __shared__ __align__(16) __nv_bfloat16 sBh[2][16 * BSTR];
    __shared__ __align__(16) __nv_bfloat16 sBl[2][16 * BSTR];

    const int tid  = threadIdx.x;
    const int lane = tid & 31;
    const int w    = tid >> 5;
    const int wm   = w & 3;
    const int wn   = w >> 2;
    const int bm   = blockIdx.y * 128;
    const int bn   = blockIdx.x * 128;

    const int ar  = tid >> 1;
    const int acg = (tid & 1) * 8;
    const int br  = tid >> 4;
    const int bc  = (tid & 15) * 8;

    const __nv_bfloat16* gAh = Ah + (size_t)(bm + ar) * K + acg;
    const __nv_bfloat16* gAl = Al + (size_t)(bm + ar) * K + acg;
    const __nv_bfloat16* gBh = Bh + (size_t)br * N + bn + bc;
    const __nv_bfloat16* gBl = Bl + (size_t)br * N + bn + bc;

    int a_off[2];
#pragma unroll
    for (int mi = 0; mi < 2; mi++) {
        int row = wm * 32 + mi * 16 + (lane & 15);
        int col = (lane >> 4) * 8;
        a_off[mi] = row * ASTR + col;
    }
    int b_off[4];
    {
        int krow = lane & 15;
#pragma unroll
        for (int p = 0; p < 4; p++) {
            int col = wn * 64 + (p * 2 + (lane >> 4)) * 8;
            b_off[p] = krow * BSTR + col;
        }
    }

    float c[2][8][4];
#pragma unroll
    for (int mi = 0; mi < 2; mi++)
#pragma unroll
        for (int ni = 0; ni < 8; ni++)
#pragma unroll
            for (int e = 0; e < 4; e++) c[mi][ni][e] = 0.f;

    // prologue: tile 0 -> buf 0
    {
        uint4 vah  = *(const uint4*)gAh;
        uint4 val_ = *(const uint4*)gAl;
        uint4 vbh  = *(const uint4*)gBh;
        uint4 vbl  = *(const uint4*)gBl;
        *(uint4*)&sAh[0][ar * ASTR + acg] = vah;
        *(uint4*)&sAl[0][ar * ASTR + acg] = val_;
        *(uint4*)&sBh[0][br * BSTR + bc]  = vbh;
        *(uint4*)&sBl[0][br * BSTR + bc]  = vbl;
    }
    __syncthreads();

    const int nk = K >> 4;
    uint4 pah, pal, pbh, pbl;
    for (int kt = 0; kt < nk; kt++) {
        const int buf = kt & 1;
        if (kt + 1 < nk) {
            int k0 = (kt + 1) * 16;
            pah = *(const uint4*)(gAh + k0);
            pal = *(const uint4*)(gAl + k0);
            pbh = *(const uint4*)(gBh + (size_t)k0 * N);
            pbl = *(const uint4*)(gBl + (size_t)k0 * N);
        }

        uint32_t fah[2][4], fal[2][4], fbh[8][2], fbl[8][2];
#pragma unroll
        for (int mi = 0; mi < 2; mi++) {
            ldsm4(fah[mi], &sAh[buf][a_off[mi]]);
            ldsm4(fal[mi], &sAl[buf][a_off[mi]]);
        }
#pragma unroll
        for (int p = 0; p < 4; p++) {
            uint32_t r[4];
            ldsm4t(r, &sBh[buf][b_off[p]]);
            fbh[p * 2][0] = r[0]; fbh[p * 2][1] = r[1];
            fbh[p * 2 + 1][0] = r[2]; fbh[p * 2 + 1][1] = r[3];
            ldsm4t(r, &sBl[buf][b_off[p]]);
            fbl[p * 2][0] = r[0]; fbl[p * 2][1] = r[1];
            fbl[p * 2 + 1][0] = r[2]; fbl[p * 2 + 1][1] = r[3];
        }

#pragma unroll
        for (int mi = 0; mi < 2; mi++)
#pragma unroll
            for (int ni = 0; ni < 8; ni++) mma16816(c[mi][ni], fah[mi], fbh[ni]);
#pragma unroll
        for (int mi = 0; mi < 2; mi++)
#pragma unroll
            for (int ni = 0; ni < 8; ni++) mma16816(c[mi][ni], fah[mi], fbl[ni]);
#pragma unroll
        for (int mi = 0; mi < 2; mi++)
#pragma unroll
            for (int ni = 0; ni < 8; ni++) mma16816(c[mi][ni], fal[mi], fbh[ni]);

        // store prefetched tile into the OTHER buffer; safe without a prior
        // barrier: buf^1's readers finished before the barrier at the end of
        // the previous iteration.
        if (kt + 1 < nk) {
            const int nb = buf ^ 1;
            *(uint4*)&sAh[nb][ar * ASTR + acg] = pah;
            *(uint4*)&sAl[nb][ar * ASTR + acg] = pal;
            *(uint4*)&sBh[nb][br * BSTR + bc]  = pbh;
            *(uint4*)&sBl[nb][br * BSTR + bc]  = pbl;
            __syncthreads();
        }
    }

    // epilogue
    const int er = lane >> 2;
    const int ec = (lane & 3) * 2;
#pragma unroll
    for (int mi = 0; mi < 2; mi++) {
#pragma unroll
        for (int ni = 0; ni < 8; ni++) {
            int r0 = bm + wm * 32 + mi * 16 + er;
            int cc = bn + wn * 64 + ni * 8 + ec;
            float v0 = c[mi][ni][0], v1 = c[mi][ni][1];
            float v2 = c[mi][ni][2], v3 = c[mi][ni][3];
            if (EPI >= 1) {
                float bi0 = bias[cc], bi1 = bias[cc + 1];
                v0 += bi0; v1 += bi1; v2 += bi0; v3 += bi1;
            }
            if (EPI == 3) {
                v0 = fmaxf(v0, 0.f); v1 = fmaxf(v1, 0.f);
                v2 = fmaxf(v2, 0.f); v3 = fmaxf(v3, 0.f);
                __nv_bfloat16 h0 = __float2bfloat16(v0);
                __nv_bfloat16 h1 = __float2bfloat16(v1);
                __nv_bfloat16 h2 = __float2bfloat16(v2);
                __nv_bfloat16 h3 = __float2bfloat16(v3);
                __nv_bfloat162 hp0; hp0.x = h0; hp0.y = h1;
                __nv_bfloat162 hp1; hp1.x = h2; hp1.y = h3;
                __nv_bfloat162 lp0;
                lp0.x = __float2bfloat16(v0 - __bfloat162float(h0));
                lp0.y = __float2bfloat16(v1 - __bfloat162float(h1));
                __nv_bfloat162 lp1;
                lp1.x = __float2bfloat16(v2 - __bfloat162float(h2));
                lp1.y = __float2bfloat16(v3 - __bfloat162float(h3));
                *reinterpret_cast<__nv_bfloat162*>(&Ch[(size_t)r0 * N + cc])       = hp0;
                *reinterpret_cast<__nv_bfloat162*>(&Cl[(size_t)r0 * N + cc])       = lp0;
                *reinterpret_cast<__nv_bfloat162*>(&Ch[(size_t)(r0 + 8) * N + cc]) = hp1;
                *reinterpret_cast<__nv_bfloat162*>(&Cl[(size_t)(r0 + 8) * N + cc]) = lp1;
            } else {
                *(float2*)&C[(size_t)r0 * N + cc]       = make_float2(v0, v1);
                *(float2*)&C[(size_t)(r0 + 8) * N + cc] = make_float2(v2, v3);
            }
        }
    }
}

// ===========================================================================
// Attention (fp32 SIMT) reading fused QKV [NTOK, 2304]; ctx -> bf16 split.
// ===========================================================================
__global__ __launch_bounds__(256) void attn_kernel(
    const float* __restrict__ QKV,
    __nv_bfloat16* __restrict__ Oh, __nv_bfloat16* __restrict__ Ol)
{
    extern __shared__ float sm[];
    float* sQ  = sm;
    float* sK  = sQ + 2048;
    float* sKt = sK + 4096;
    float* sS  = sKt + 4352;

    const int qt  = blockIdx.x;
    const int h   = blockIdx.y;
    const int b   = blockIdx.z;
    const int tid = threadIdx.x;
    const size_t base = (size_t)b * SEQ * QKVN + h * DK;

    for (int i = tid; i < 512; i += 256) {
        int r = i >> 4, cx = (i & 15) * 4;
        *(float4*)&sQ[r * 64 + cx] =
            *(const float4*)&QKV[base + (size_t)(qt * 32 + r) * QKVN + cx];
    }

    const int gq  = tid >> 4;
    const int gk  = tid & 15;
    const int qi0 = gq * 2;
    const int kj0 = gk * 4;

    for (int kt = 0; kt < 8; kt++) {
        __syncthreads();
        for (int i = tid; i < 1024; i += 256) {
            int r = i >> 4, cx = (i & 15) * 4;
            *(float4*)&sK[r * 64 + cx] =
                *(const float4*)&QKV[base + 768 + (size_t)(kt * 64 + r) * QKVN + cx];
        }
        __syncthreads();
        for (int i = tid; i < 4096; i += 256) {
            int d = i & 63, r = i >> 6;
            sKt[d * 68 + r] = sK[r * 64 + d];
        }
        __syncthreads();

        float acc[2][4] = {{0.f,0.f,0.f,0.f},{0.f,0.f,0.f,0.f}};
#pragma unroll 8
        for (int d = 0; d < 64; d++) {
            float q0 = sQ[qi0 * 64 + d];
            float q1 = sQ[qi0 * 64 + 64 + d];
            float4 kv = *(float4*)&sKt[d * 68 + kj0];
            acc[0][0] += q0 * kv.x; acc[0][1] += q0 * kv.y;
            acc[0][2] += q0 * kv.z; acc[0][3] += q0 * kv.w;
            acc[1][0] += q1 * kv.x; acc[1][1] += q1 * kv.y;
            acc[1][2] += q1 * kv.z; acc[1][3] += q1 * kv.w;
        }
#pragma unroll
        for (int i = 0; i < 2; i++)
#pragma unroll
            for (int j = 0; j < 4; j++)
                sS[(qi0 + i) * 512 + kt * 64 + kj0 + j] = acc[i][j] * 0.125f;
    }
    __syncthreads();

    {
        const int wid = tid >> 5, lanei = tid & 31;
        for (int r = wid * 4; r < wid * 4 + 4; r++) {
            float* srow = sS + r * 512;
            float m = -1e30f;
            for (int cx = lanei; cx < 512; cx += 32) m = fmaxf(m, srow[cx]);
#pragma unroll
            for (int o = 16; o > 0; o >>= 1)
                m = fmaxf(m, __shfl_xor_sync(0xffffffffu, m, o));
            float s = 0.f;
            for (int cx = lanei; cx < 512; cx += 32) {
                float e = __expf(srow[cx] - m);
                srow[cx] = e;
                s += e;
            }
#pragma unroll
            for (int o = 16; o > 0; o >>= 1)
                s += __shfl_xor_sync(0xffffffffu, s, o);
            float inv = 1.0f / s;
            for (int cx = lanei; cx < 512; cx += 32) srow[cx] *= inv;
        }
    }

    const int d0 = gk * 4;
    float o_[2][4] = {{0.f,0.f,0.f,0.f},{0.f,0.f,0.f,0.f}};
    for (int kt = 0; kt < 8; kt++) {
        __syncthreads();
        for (int i = tid; i < 1024; i += 256) {
            int r = i >> 4, cx = (i & 15) * 4;
            *(float4*)&sK[r * 64 + cx] =
                *(const float4*)&QKV[base + 1536 + (size_t)(kt * 64 + r) * QKVN + cx];
        }
        __syncthreads();
#pragma unroll 4
        for (int k = 0; k < 64; k++) {
            float s0 = sS[qi0 * 512 + kt * 64 + k];
            float s1 = sS[qi0 * 512 + 512 + kt * 64 + k];
            float4 vv = *(float4*)&sK[k * 64 + d0];
            o_[0][0] += s0 * vv.x; o_[0][1] += s0 * vv.y;
            o_[0][2] += s0 * vv.z; o_[0][3] += s0 * vv.w;
            o_[1][0] += s1 * vv.x; o_[1][1] += s1 * vv.y;
            o_[1][2] += s1 * vv.z; o_[1][3] += s1 * vv.w;
        }
    }

#pragma unroll
    for (int i = 0; i < 2; i++) {
        size_t idx = ((size_t)b * SEQ + qt * 32 + qi0 + i) * EMB + h * DK + d0;
        __nv_bfloat16 h0 = __float2bfloat16(o_[i][0]);
        __nv_bfloat16 h1 = __float2bfloat16(o_[i][1]);
        __nv_bfloat16 h2 = __float2bfloat16(o_[i][2]);
        __nv_bfloat16 h3 = __float2bfloat16(o_[i][3]);
        __nv_bfloat162 hp0; hp0.x = h0; hp0.y = h1;
        __nv_bfloat162 hp1; hp1.x = h2; hp1.y = h3;
        __nv_bfloat162 lp0;
        lp0.x = __float2bfloat16(o_[i][0] - __bfloat162float(h0));
        lp0.y = __float2bfloat16(o_[i][1] - __bfloat162float(h1));
        __nv_bfloat162 lp1;
        lp1.x = __float2bfloat16(o_[i][2] - __bfloat162float(h2));
        lp1.y = __float2bfloat16(o_[i][3] - __bfloat162float(h3));
        *reinterpret_cast<__nv_bfloat162*>(&Oh[idx])     = hp0;
        *reinterpret_cast<__nv_bfloat162*>(&Oh[idx + 2]) = hp1;
        *reinterpret_cast<__nv_bfloat162*>(&Ol[idx])     = lp0;
        *reinterpret_cast<__nv_bfloat162*>(&Ol[idx + 2]) = lp1;
    }
}

// ===========================================================================
// Fused residual + LayerNorm (+ optional bf16 split out)
// ===========================================================================
__global__ __launch_bounds__(256) void add_ln_kernel(
    const float* __restrict__ x, const float* __restrict__ r,
    const float* __restrict__ gamma, const float* __restrict__ beta,
    float* __restrict__ out,
    __nv_bfloat16* __restrict__ oh, __nv_bfloat16* __restrict__ ol)
{
    const int row = blockIdx.x;
    const int tid = threadIdx.x;
    const float* xr = x + (size_t)row * EMB;
    const float* rr = r + (size_t)row * EMB;

    float v[3];
    float s = 0.f;
#pragma unroll
    for (int i = 0; i < 3; i++) {
        int cx = tid + i * 256;
        float t = xr[cx] + rr[cx];
        v[i] = t;
        s += t;
    }

    __shared__ float red[8];
    const int wid = tid >> 5, lane = tid & 31;
#pragma unroll
    for (int o = 16; o > 0; o >>= 1) s += __shfl_xor_sync(0xffffffffu, s, o);
    if (lane == 0) red[wid] = s;
    __syncthreads();
    if (tid == 0) {
        float t = 0.f;
#pragma unroll
        for (int i = 0; i < 8; i++) t += red[i];
        red[0] = t;
    }
    __syncthreads();
    const float mean = red[0] * (1.0f / 768.0f);

    float s2 = 0.f;
#pragma unroll
    for (int i = 0; i < 3; i++) {
        float d = v[i] - mean;
        s2 += d * d;
    }
#pragma unroll
    for (int o = 16; o > 0; o >>= 1) s2 += __shfl_xor_sync(0xffffffffu, s2, o);
    __syncthreads();
    if (lane == 0) red[wid] = s2;
    __syncthreads();
    if (tid == 0) {
        float t = 0.f;
#pragma unroll
        for (int i = 0; i < 8; i++) t += red[i];
        red[0] = t;
    }
    __syncthreads();
    const float var  = red[0] * (1.0f / 768.0f);
    const float rstd = rsqrtf(var + 1e-5f);

#pragma unroll
    for (int i = 0; i < 3; i++) {
        int cx = tid + i * 256;
        float o = (v[i] - mean) * rstd * gamma[cx] + beta[cx];
        size_t idx = (size_t)row * EMB + cx;
        out[idx] = o;
        if (oh) {
            __nv_bfloat16 hh = __float2bfloat16(o);
            oh[idx] = hh;
            ol[idx] = __float2bfloat16(o - __bfloat162float(hh));
        }
    }
}

// ===========================================================================
// Launch
// ===========================================================================
extern "C" void kernel_launch(void* const* d_in, const int* in_sizes, int n_in,
                              void* d_out, int out_size)
{
    (void)in_sizes; (void)n_in; (void)out_size;

    const float* x   = (const float*)d_in[0];
    const float* Wq  = (const float*)d_in[1];
    const float* Wk  = (const float*)d_in[2];
    const float* Wv  = (const float*)d_in[3];
    const float* Wo  = (const float*)d_in[4];
    const float* W1  = (const float*)d_in[5];
    const float* b1  = (const float*)d_in[6];
    const float* W2  = (const float*)d_in[7];
    const float* b2  = (const float*)d_in[8];
    const float* g1  = (const float*)d_in[9];
    const float* be1 = (const float*)d_in[10];
    const float* g2  = (const float*)d_in[11];
    const float* be2 = (const float*)d_in[12];
    float* out = (float*)d_out;

    float *qkv, *tmp, *x1;
    __nv_bfloat16 *ah, *al, *ch, *cl, *fh, *fl, *wh, *wl;
    cudaGetSymbolAddress((void**)&qkv, g_qkv);
    cudaGetSymbolAddress((void**)&tmp, g_tmp);
    cudaGetSymbolAddress((void**)&x1,  g_x1);
    cudaGetSymbolAddress((void**)&ah,  g_ah);
    cudaGetSymbolAddress((void**)&al,  g_al);
    cudaGetSymbolAddress((void**)&ch,  g_ch);
    cudaGetSymbolAddress((void**)&cl,  g_cl);
    cudaGetSymbolAddress((void**)&fh,  g_fh);
    cudaGetSymbolAddress((void**)&fl,  g_fl);
    cudaGetSymbolAddress((void**)&wh,  g_wh);
    cudaGetSymbolAddress((void**)&wl,  g_wl);

    const int ATTN_SMEM = (2048 + 4096 + 64 * 68 + 16384) * 4;
    cudaFuncSetAttribute(attn_kernel,
                         cudaFuncAttributeMaxDynamicSharedMemorySize, ATTN_SMEM);

    const size_t EE = (size_t)EMB * EMB;
    const size_t EF = (size_t)EMB * FFND;
    const size_t OQKV = 0, OO_ = 3 * EE, O1_ = 4 * EE, O2_ = 4 * EE + EF;

    dim3 blk(256);

    // activation split (x)
    split_kernel<<<NTOK * EMB / 1024, blk>>>(x, ah, al, NTOK * EMB);
    // weight splits; Wq/Wk/Wv scatter into merged [768,2304] buffer
    splitw_kernel<<<(int)(EE / 1024), blk>>>(Wq, wh + OQKV, wl + OQKV, EMB, QKVN, 0,    (int)EE);
    splitw_kernel<<<(int)(EE / 1024), blk>>>(Wk, wh + OQKV, wl + OQKV, EMB, QKVN, 768,  (int)EE);
    splitw_kernel<<<(int)(EE / 1024), blk>>>(Wv, wh + OQKV, wl + OQKV, EMB, QKVN, 1536, (int)EE);
    splitw_kernel<<<(int)(EE / 1024), blk>>>(Wo, wh + OO_,  wl + OO_,  EMB, EMB,  0,    (int)EE);
    splitw_kernel<<<(int)(EF / 1024), blk>>>(W1, wh + O1_,  wl + O1_,  FFND, FFND, 0,   (int)EF);
    splitw_kernel<<<(int)(EF / 1024), blk>>>(W2, wh + O2_,  wl + O2_,  EMB,  EMB,  0,   (int)EF);

    // fused QKV projection: [NTOK,768] @ [768,2304]
    tgemm<0><<<dim3(QKVN / 128, NTOK / 128), blk>>>(
        ah, al, wh + OQKV, wl + OQKV, nullptr, qkv, nullptr, nullptr, NTOK, QKVN, EMB);

    // attention -> ctx (bf16 split)
    attn_kernel<<<dim3(SEQ / 32, HEADS, BATCH), blk, ATTN_SMEM>>>(qkv, ch, cl);

    // output projection
    tgemm<0><<<dim3(EMB / 128, NTOK / 128), blk>>>(
        ch, cl, wh + OO_, wl + OO_, nullptr, tmp, nullptr, nullptr, NTOK, EMB, EMB);

    // residual + LN1 (emits x1 split into ah/al)
    add_ln_kernel<<<NTOK, blk>>>(x, tmp, g1, be1, x1, ah, al);

    // FFN
    tgemm<3><<<dim3(FFND / 128, NTOK / 128), blk>>>(
        ah, al, wh + O1_, wl + O1_, b1, nullptr, fh, fl, NTOK, FFND, EMB);
    tgemm<1><<<dim3(EMB / 128, NTOK / 128), blk>>>(
        fh, fl, wh + O2_, wl + O2_, b2, tmp, nullptr, nullptr, NTOK, EMB, FFND);

    // residual + LN2
    add_ln_kernel<<<NTOK, blk>>>(x1, tmp, g2, be2, out, nullptr, nullptr);
}